// round 15
// baseline (speedup 1.0000x reference)
#include <cuda_runtime.h>
#include <cuda_bf16.h>
#include <cstdint>

// Problem constants
#define NW   8192
#define NTOK 64
#define CDIM 180
#define HEADS 6
#define HD   30
#define NW_PER_IMG 1024
#define NTASK (NW * HEADS)

// Scratch (allocation-guard-safe: __device__ globals)
__device__ float g_qkv[(long long)NW * NTOK * (3 * CDIM)];   // rounded, q pre-scaled
__device__ float g_att[(long long)NW * NTOK * CDIM];         // rounded-x, then attn out
__device__ float g_bias6[HEADS * NTOK * NTOK];               // rpb expanded
__device__ float g_wq[3 * CDIM * CDIM];                      // rounded (+q-scaled) qkv_w
__device__ float g_wp[CDIM * CDIM];                          // rounded proj_w
__device__ float g_bq[3 * CDIM];                             // q-scaled qkv_b

// ===========================================================================
// tf32 helpers
// ===========================================================================
__device__ __forceinline__ float f2tf32(float x) {
    unsigned u;
    asm("cvt.rna.tf32.f32 %0, %1;" : "=r"(u) : "f"(x));
    return __uint_as_float(u);
}

__device__ __forceinline__ void mma_tf32(float d[4], const float a[4], const float b[2]) {
    const unsigned* A = reinterpret_cast<const unsigned*>(a);
    const unsigned* B = reinterpret_cast<const unsigned*>(b);
    asm volatile(
        "mma.sync.aligned.m16n8k8.row.col.f32.tf32.tf32.f32 "
        "{%0,%1,%2,%3},{%4,%5,%6,%7},{%8,%9},{%0,%1,%2,%3};\n"
        : "+f"(d[0]), "+f"(d[1]), "+f"(d[2]), "+f"(d[3])
        : "r"(A[0]), "r"(A[1]), "r"(A[2]), "r"(A[3]), "r"(B[0]), "r"(B[1]));
}

__device__ __forceinline__ void cp_async16(unsigned dst, const void* src, int src_bytes) {
    asm volatile("cp.async.cg.shared.global [%0], [%1], 16, %2;\n"
                 :: "r"(dst), "l"(src), "r"(src_bytes));
}
__device__ __forceinline__ void cp_async16u(unsigned dst, const void* src) {
    asm volatile("cp.async.cg.shared.global [%0], [%1], 16;\n"
                 :: "r"(dst), "l"(src));
}
__device__ __forceinline__ void cp_async8(unsigned dst, const void* src) {
    asm volatile("cp.async.ca.shared.global [%0], [%1], 8;\n"
                 :: "r"(dst), "l"(src));
}
__device__ __forceinline__ void cp_commit() {
    asm volatile("cp.async.commit_group;\n" ::: "memory");
}
__device__ __forceinline__ void cp_wait1() {
    asm volatile("cp.async.wait_group 1;\n" ::: "memory");
}

// ===========================================================================
// Prep kernels
// ===========================================================================
__global__ void round_kernel(const float* __restrict__ in, float* __restrict__ out, int n4)
{
    int i = blockIdx.x * blockDim.x + threadIdx.x;
    for (; i < n4; i += gridDim.x * blockDim.x) {
        float4 v = ((const float4*)in)[i];
        v.x = f2tf32(v.x); v.y = f2tf32(v.y);
        v.z = f2tf32(v.z); v.w = f2tf32(v.w);
        ((float4*)out)[i] = v;
    }
}

// qkv_w: round, scale rows < 180 (q out-channels) by 1/sqrt(hd)
__global__ void round_wq_kernel(const float* __restrict__ in, float* __restrict__ out)
{
    const float scale = rsqrtf((float)HD);
    int i = blockIdx.x * blockDim.x + threadIdx.x;
    const int n4 = 3 * CDIM * CDIM / 4;
    for (; i < n4; i += gridDim.x * blockDim.x) {
        float s = ((i * 4) / CDIM) < CDIM ? scale : 1.f;
        float4 v = ((const float4*)in)[i];
        v.x = f2tf32(v.x * s); v.y = f2tf32(v.y * s);
        v.z = f2tf32(v.z * s); v.w = f2tf32(v.w * s);
        ((float4*)out)[i] = v;
    }
}

__global__ void scale_bq_kernel(const float* __restrict__ qkv_b)
{
    const float scale = rsqrtf((float)HD);
    int i = threadIdx.x;
    if (i < 3 * CDIM) g_bq[i] = i < CDIM ? qkv_b[i] * scale : qkv_b[i];
}

__global__ void bias_expand_kernel(const float* __restrict__ rpb)
{
    const int h = blockIdx.x;
    for (int i = threadIdx.x; i < NTOK * NTOK; i += blockDim.x) {
        int r = i >> 6, c = i & 63;
        int idx = ((r >> 3) - (c >> 3) + 7) * 15 + ((r & 7) - (c & 7) + 7);
        g_bias6[h * NTOK * NTOK + i] = rpb[idx * HEADS + h];
    }
}

// ===========================================================================
// GEMM (TN): C[M,N] = A[M,180] @ B[N,180]^T + bias[N]; optional tf32-round
// of the output (for QKV -> attention).
// ===========================================================================
#define GROWS 36
#define GSTAGE_WORDS (256 * GROWS)
#define GNITER 6

__global__ __launch_bounds__(256, 2) void mma_gemm_tn(
    const float* __restrict__ A, const float* __restrict__ B,
    const float* __restrict__ bias, float* __restrict__ C, int N, int roundOut)
{
    extern __shared__ float sm[];
    const int tid = threadIdx.x;
    const int row0 = blockIdx.y * 128;
    const int col0 = blockIdx.x * 128;

    const unsigned sbase = (unsigned)__cvta_generic_to_shared(sm);

    auto stage_load = [&](int s, int ki) {
        const int k0 = ki * 32;
        const unsigned stW = sbase + (unsigned)(s * GSTAGE_WORDS) * 4u;
#pragma unroll
        for (int j = 0; j < 8; j++) {
            int idx = tid + j * 256;
            int r  = (idx & 1023) >> 3;
            int c4 = idx & 7;
            int gk = k0 + c4 * 4;
            int gkc = gk <= 176 ? gk : 176;
            if (idx < 1024) {
                int bytes = (gk <= 176) ? 16 : 0;
                const float* src = A + (size_t)(row0 + r) * CDIM + gkc;
                cp_async16(stW + (unsigned)(r * GROWS + c4 * 4) * 4u, src, bytes);
            } else {
                int nn = col0 + r;
                int ok = (nn < N) && (gk <= 176);
                const float* src = B + (size_t)(ok ? nn : 0) * CDIM + gkc;
                cp_async16(stW + (unsigned)(128 * GROWS + r * GROWS + c4 * 4) * 4u,
                           src, ok ? 16 : 0);
            }
        }
    };

    stage_load(0, 0); cp_commit();
    stage_load(1, 1); cp_commit();
    cp_wait1();
    __syncthreads();

    const int warp = tid >> 5;
    const int lane = tid & 31;
    const int wm = warp & 1;
    const int wn = warp >> 1;
    const int g = lane >> 2;
    const int t = lane & 3;

    float acc[4][4][4];
#pragma unroll
    for (int mt = 0; mt < 4; mt++)
#pragma unroll
        for (int nt = 0; nt < 4; nt++)
#pragma unroll
            for (int e = 0; e < 4; e++) acc[mt][nt][e] = 0.f;

#pragma unroll 1
    for (int ks = 0; ks < GNITER; ks++) {
        if (ks + 2 < GNITER) stage_load((ks + 2) % 3, ks + 2);
        cp_commit();

        const float* sA = sm + (ks % 3) * GSTAGE_WORDS;
        const float* sB = sA + 128 * GROWS;

#pragma unroll
        for (int step = 0; step < 4; step++) {
            const int kb = step * 8;
            float a[4][4], b[4][2];
#pragma unroll
            for (int mt = 0; mt < 4; mt++) {
                int base = (wm * 64 + mt * 16 + g) * GROWS + kb + t;
                a[mt][0] = sA[base];
                a[mt][1] = sA[base + 8 * GROWS];
                a[mt][2] = sA[base + 4];
                a[mt][3] = sA[base + 8 * GROWS + 4];
            }
#pragma unroll
            for (int nt = 0; nt < 4; nt++) {
                int bb = (wn * 32 + nt * 8 + g) * GROWS + kb + t;
                b[nt][0] = sB[bb];
                b[nt][1] = sB[bb + 4];
            }
#pragma unroll
            for (int mt = 0; mt < 4; mt++)
#pragma unroll
                for (int nt = 0; nt < 4; nt++)
                    mma_tf32(acc[mt][nt], a[mt], b[nt]);
        }
        cp_wait1();
        __syncthreads();
    }

#pragma unroll
    for (int mt = 0; mt < 4; mt++) {
#pragma unroll
        for (int nt = 0; nt < 4; nt++) {
            int row = row0 + wm * 64 + mt * 16 + g;
            int col = col0 + wn * 32 + nt * 8 + 2 * t;
            if (col < N) {
                float b0 = bias[col], b1 = bias[col + 1];
                float e0 = acc[mt][nt][0] + b0, e1 = acc[mt][nt][1] + b1;
                float e2 = acc[mt][nt][2] + b0, e3 = acc[mt][nt][3] + b1;
                if (roundOut) {
                    e0 = f2tf32(e0); e1 = f2tf32(e1);
                    e2 = f2tf32(e2); e3 = f2tf32(e3);
                }
                *(float2*)(C + (size_t)row * N + col) = make_float2(e0, e1);
                *(float2*)(C + (size_t)(row + 8) * N + col) = make_float2(e2, e3);
            }
        }
    }
}

// ===========================================================================
// Persistent pipelined MMA attention.
// Grid = 296 blocks (2/SM), 128 threads (4 warps). Each block loops over
// tasks (wi-major: task -> wi, img, h). Double-buffered task staging via
// cp.async (pure byte copy: qkv already tf32-rounded + q-scaled by GEMM).
// Per-task buffer (floats): q[64][36], k[64][36], v[64][36], mask[64][68]
//   = 11264. Two buffers + P stripes 4*16*68 = 4352.
// Total smem 27008... = 2*11264 + 4352 = 26880 floats = 107520 B.
// K/V pad cols 30..35 zeroed once (cp.async never writes them).
// ===========================================================================
#define TASK_FLOATS 11264
#define TB_MASK 6912
#define ATT_SMEM_BYTES ((2 * TASK_FLOATS + 4352) * 4)

__global__ __launch_bounds__(128, 2) void attn_pipe_kernel(
    const float* __restrict__ qkv, const float* __restrict__ mask,
    float* __restrict__ out)
{
    extern __shared__ float sm[];
    const int tid = threadIdx.x;
    const unsigned sbase = (unsigned)__cvta_generic_to_shared(sm);

    // ---- prefetch one task's q/k/v + mask into buffer `buf` ----
    auto prefetch = [&](int buf, int task) {
        const int wi = task / (8 * HEADS);
        const int sub = task - wi * (8 * HEADS);
        const int img = sub / HEADS;
        const int h = sub - img * HEADS;
        const int w = img * NW_PER_IMG + wi;
        const float* qbase = qkv + (size_t)w * NTOK * (3 * CDIM) + h * HD;
        const unsigned sb = sbase + (unsigned)(buf * TASK_FLOATS) * 4u;
#pragma unroll
        for (int j = 0; j < 23; j++) {
            int i = tid + j * 128;
            if (i < 2880) {
                int arr = i / 960;
                int rem = i - arr * 960;
                int r = rem / 15, c2 = rem - r * 15;
                const float* src = qbase + (size_t)r * (3 * CDIM) + arr * CDIM + c2 * 2;
                cp_async8(sb + (unsigned)(arr * 2304 + r * 36 + c2 * 2) * 4u, src);
            }
        }
        const float* mbase = mask + (size_t)wi * NTOK * NTOK;
#pragma unroll
        for (int j = 0; j < 8; j++) {
            int i = tid + j * 128;
            int r = i >> 4, c = (i & 15) * 4;
            cp_async16u(sb + (unsigned)(TB_MASK + r * 68 + c) * 4u, mbase + r * 64 + c);
        }
        cp_commit();
    };

    // ---- zero K/V/Q pad cols 30..35 in both buffers (once) ----
    for (int i = tid; i < 2304; i += 128) {
        int buf = i / 1152;
        int rem = i - buf * 1152;
        int arr = rem / 384;
        int rem2 = rem - arr * 384;
        int r = rem2 / 6, c = 30 + (rem2 - r * 6);
        sm[buf * TASK_FLOATS + arr * 2304 + r * 36 + c] = 0.f;
    }

    const int ws = tid >> 5;
    const int lane = tid & 31;
    const int g = lane >> 2;
    const int t = lane & 3;
    float* sP = sm + 2 * TASK_FLOATS + ws * 1088;

    int task = blockIdx.x;
    const int stride = gridDim.x;
    prefetch(0, task);
    int buf = 0;

#pragma unroll 1
    for (; task < NTASK; task += stride) {
        int nxt = task + stride < NTASK ? task + stride : task;
        prefetch(buf ^ 1, nxt);
        cp_wait1();          // current buffer's group complete
        __syncthreads();     // staging visible to all (also covers pad zeros)

        // decompose current task
        const int wi = task / (8 * HEADS);
        const int sub = task - wi * (8 * HEADS);
        const int img = sub / HEADS;
        const int h = sub - img * HEADS;
        const int w = img * NW_PER_IMG + wi;

        const float* B = sm + buf * TASK_FLOATS;
        const float* sQ = B;
        const float* sK = B + 2304;
        const float* sV = B + 4608;
        const float* sMk = B + TB_MASK;
        const float* gb = g_bias6 + h * NTOK * NTOK;
        const int row_g = ws * 16 + g;

        // bias+mask preload into regs
        float2 bia0[8], bia1[8];
#pragma unroll
        for (int nt = 0; nt < 8; nt++) {
            int c = nt * 8 + 2 * t;
            float2 gb0 = *(const float2*)(gb + row_g * 64 + c);
            float2 gb1 = *(const float2*)(gb + (row_g + 8) * 64 + c);
            float2 m0 = *(const float2*)(sMk + row_g * 68 + c);
            float2 m1 = *(const float2*)(sMk + (row_g + 8) * 68 + c);
            bia0[nt] = make_float2(gb0.x + m0.x, gb0.y + m0.y);
            bia1[nt] = make_float2(gb1.x + m1.x, gb1.y + m1.y);
        }

        // Q a-fragments
        float qa[4][4];
#pragma unroll
        for (int kc = 0; kc < 4; kc++) {
            qa[kc][0] = sQ[row_g * 36 + kc * 8 + t];
            qa[kc][1] = sQ[(row_g + 8) * 36 + kc * 8 + t];
            qa[kc][2] = sQ[row_g * 36 + kc * 8 + t + 4];
            qa[kc][3] = sQ[(row_g + 8) * 36 + kc * 8 + t + 4];
        }

        // scores + exp + P store
        float rs0 = 0.f, rs1 = 0.f;
#pragma unroll
        for (int nt = 0; nt < 8; nt++) {
            float acc[4] = {0.f, 0.f, 0.f, 0.f};
#pragma unroll
            for (int kc = 0; kc < 4; kc++) {
                float b2[2];
                b2[0] = sK[(nt * 8 + g) * 36 + kc * 8 + t];
                b2[1] = sK[(nt * 8 + g) * 36 + kc * 8 + t + 4];
                mma_tf32(acc, qa[kc], b2);
            }
            float p0 = f2tf32(__expf(acc[0] + bia0[nt].x));
            float p1 = f2tf32(__expf(acc[1] + bia0[nt].y));
            float p2 = f2tf32(__expf(acc[2] + bia1[nt].x));
            float p3 = f2tf32(__expf(acc[3] + bia1[nt].y));
            rs0 += p0 + p1;
            rs1 += p2 + p3;
            *(float2*)(sP + g * 68 + nt * 8 + 2 * t) = make_float2(p0, p1);
            *(float2*)(sP + (g + 8) * 68 + nt * 8 + 2 * t) = make_float2(p2, p3);
        }
        rs0 += __shfl_xor_sync(0xffffffffu, rs0, 1);
        rs0 += __shfl_xor_sync(0xffffffffu, rs0, 2);
        rs1 += __shfl_xor_sync(0xffffffffu, rs1, 1);
        rs1 += __shfl_xor_sync(0xffffffffu, rs1, 2);
        __syncwarp();

        // PV
        float oacc[4][4];
#pragma unroll
        for (int nd = 0; nd < 4; nd++)
#pragma unroll
            for (int e = 0; e < 4; e++) oacc[nd][e] = 0.f;
#pragma unroll
        for (int kc = 0; kc < 8; kc++) {
            float a[4];
            a[0] = sP[g * 68 + kc * 8 + t];
            a[1] = sP[(g + 8) * 68 + kc * 8 + t];
            a[2] = sP[g * 68 + kc * 8 + t + 4];
            a[3] = sP[(g + 8) * 68 + kc * 8 + t + 4];
#pragma unroll
            for (int nd = 0; nd < 4; nd++) {
                float b2[2];
                b2[0] = sV[(kc * 8 + t) * 36 + nd * 8 + g];
                b2[1] = sV[(kc * 8 + t + 4) * 36 + nd * 8 + g];
                mma_tf32(oacc[nd], a, b2);
            }
        }

        // normalize + write out (tf32-rounded for proj GEMM)
        const float inv0 = 1.f / rs0;
        const float inv1 = 1.f / rs1;
#pragma unroll
        for (int nd = 0; nd < 4; nd++) {
            int d = nd * 8 + 2 * t;
            if (d < HD) {
                float2 v0 = make_float2(f2tf32(oacc[nd][0] * inv0), f2tf32(oacc[nd][1] * inv0));
                float2 v1 = make_float2(f2tf32(oacc[nd][2] * inv1), f2tf32(oacc[nd][3] * inv1));
                *(float2*)(out + (size_t)(w * NTOK + row_g) * CDIM + h * HD + d) = v0;
                *(float2*)(out + (size_t)(w * NTOK + row_g + 8) * CDIM + h * HD + d) = v1;
            }
        }

        __syncthreads();   // all warps done with buf before it is re-prefetched
        buf ^= 1;
    }
}

// ===========================================================================
extern "C" void kernel_launch(void* const* d_in, const int* in_sizes, int n_in,
                              void* d_out, int out_size)
{
    const float* x      = (const float*)d_in[0];
    const float* mask   = (const float*)d_in[1];
    const float* qkv_w  = (const float*)d_in[2];
    const float* qkv_b  = (const float*)d_in[3];
    const float* proj_w = (const float*)d_in[4];
    const float* proj_b = (const float*)d_in[5];
    const float* rpb    = (const float*)d_in[6];
    float* out = (float*)d_out;

    void *p_qkv = nullptr, *p_att = nullptr, *p_wq = nullptr, *p_wp = nullptr, *p_bq = nullptr;
    cudaGetSymbolAddress(&p_qkv, g_qkv);
    cudaGetSymbolAddress(&p_att, g_att);
    cudaGetSymbolAddress(&p_wq, g_wq);
    cudaGetSymbolAddress(&p_wp, g_wp);
    cudaGetSymbolAddress(&p_bq, g_bq);
    float* qkv = (float*)p_qkv;
    float* att = (float*)p_att;   // rounded x, then attention output
    float* wq  = (float*)p_wq;
    float* wp  = (float*)p_wp;
    float* bq  = (float*)p_bq;

    const int M = NW * NTOK;                                  // 524288
    const int gemm_smem = 3 * GSTAGE_WORDS * sizeof(float);   // 110592

    static bool attr_set = false;
    if (!attr_set) {
        cudaFuncSetAttribute(mma_gemm_tn,
                             cudaFuncAttributeMaxDynamicSharedMemorySize, gemm_smem);
        cudaFuncSetAttribute(attn_pipe_kernel,
                             cudaFuncAttributeMaxDynamicSharedMemorySize, ATT_SMEM_BYTES);
        attr_set = true;
    }

    // 0) Prep: round x, round+scale qkv_w, round proj_w, scale qkv_b, expand rpb
    round_kernel<<<2048, 256>>>(x, att, M * CDIM / 4);
    round_wq_kernel<<<64, 256>>>(qkv_w, wq);
    round_kernel<<<32, 256>>>(proj_w, wp, CDIM * CDIM / 4);
    scale_bq_kernel<<<1, 3 * CDIM>>>(qkv_b);
    bias_expand_kernel<<<HEADS, 256>>>(rpb);

    // 1) QKV projection (output tf32-rounded, q pre-scaled via wq/bq)
    {
        dim3 grid((3 * CDIM + 127) / 128, M / 128);
        mma_gemm_tn<<<grid, 256, gemm_smem>>>(att, wq, bq, qkv, 3 * CDIM, 1);
    }

    // 2) Persistent pipelined attention
    attn_pipe_kernel<<<296, 128, ATT_SMEM_BYTES>>>(qkv, mask, att);

    // 3) Output projection
    {
        dim3 grid((CDIM + 127) / 128, M / 128);
        mma_gemm_tn<<<grid, 256, gemm_smem>>>(att, wp, proj_b, out, CDIM, 0);
    }
}

// round 16
// speedup vs baseline: 1.0590x; 1.0590x over previous
#include <cuda_runtime.h>
#include <cuda_bf16.h>
#include <cstdint>

// Problem constants
#define NW   8192
#define NTOK 64
#define CDIM 180
#define HEADS 6
#define HD   30
#define NW_PER_IMG 1024

// Scratch (allocation-guard-safe: __device__ globals)
__device__ float g_qkv[(long long)NW * NTOK * (3 * CDIM)];   // rounded, q pre-scaled
__device__ float g_att[(long long)NW * NTOK * CDIM];         // rounded-x, then attn out
__device__ float g_bias6[HEADS * NTOK * NTOK];               // rpb expanded
__device__ float g_wq[3 * CDIM * CDIM];                      // rounded (+q-scaled) qkv_w
__device__ float g_wp[CDIM * CDIM];                          // rounded proj_w
__device__ float g_bq[3 * CDIM];                             // q-scaled qkv_b

// ===========================================================================
// tf32 helpers
// ===========================================================================
__device__ __forceinline__ float f2tf32(float x) {
    unsigned u;
    asm("cvt.rna.tf32.f32 %0, %1;" : "=r"(u) : "f"(x));
    return __uint_as_float(u);
}

__device__ __forceinline__ void mma_tf32(float d[4], const float a[4], const float b[2]) {
    const unsigned* A = reinterpret_cast<const unsigned*>(a);
    const unsigned* B = reinterpret_cast<const unsigned*>(b);
    asm volatile(
        "mma.sync.aligned.m16n8k8.row.col.f32.tf32.tf32.f32 "
        "{%0,%1,%2,%3},{%4,%5,%6,%7},{%8,%9},{%0,%1,%2,%3};\n"
        : "+f"(d[0]), "+f"(d[1]), "+f"(d[2]), "+f"(d[3])
        : "r"(A[0]), "r"(A[1]), "r"(A[2]), "r"(A[3]), "r"(B[0]), "r"(B[1]));
}

__device__ __forceinline__ void cp_async16(unsigned dst, const void* src, int src_bytes) {
    asm volatile("cp.async.cg.shared.global [%0], [%1], 16, %2;\n"
                 :: "r"(dst), "l"(src), "r"(src_bytes));
}
__device__ __forceinline__ void cp_commit() {
    asm volatile("cp.async.commit_group;\n" ::: "memory");
}
__device__ __forceinline__ void cp_wait1() {
    asm volatile("cp.async.wait_group 1;\n" ::: "memory");
}
__device__ __forceinline__ void cp_wait0() {
    asm volatile("cp.async.wait_group 0;\n" ::: "memory");
}

// ===========================================================================
// Prep kernels
// ===========================================================================
__global__ void round_kernel(const float* __restrict__ in, float* __restrict__ out, int n4)
{
    int i = blockIdx.x * blockDim.x + threadIdx.x;
    for (; i < n4; i += gridDim.x * blockDim.x) {
        float4 v = ((const float4*)in)[i];
        v.x = f2tf32(v.x); v.y = f2tf32(v.y);
        v.z = f2tf32(v.z); v.w = f2tf32(v.w);
        ((float4*)out)[i] = v;
    }
}

// qkv_w: round, scale rows < 180 (q out-channels) by 1/sqrt(hd)
__global__ void round_wq_kernel(const float* __restrict__ in, float* __restrict__ out)
{
    const float scale = rsqrtf((float)HD);
    int i = blockIdx.x * blockDim.x + threadIdx.x;
    const int n4 = 3 * CDIM * CDIM / 4;
    for (; i < n4; i += gridDim.x * blockDim.x) {
        float s = ((i * 4) / CDIM) < CDIM ? scale : 1.f;
        float4 v = ((const float4*)in)[i];
        v.x = f2tf32(v.x * s); v.y = f2tf32(v.y * s);
        v.z = f2tf32(v.z * s); v.w = f2tf32(v.w * s);
        ((float4*)out)[i] = v;
    }
}

__global__ void scale_bq_kernel(const float* __restrict__ qkv_b)
{
    const float scale = rsqrtf((float)HD);
    int i = threadIdx.x;
    if (i < 3 * CDIM) g_bq[i] = i < CDIM ? qkv_b[i] * scale : qkv_b[i];
}

__global__ void bias_expand_kernel(const float* __restrict__ rpb)
{
    const int h = blockIdx.x;
    for (int i = threadIdx.x; i < NTOK * NTOK; i += blockDim.x) {
        int r = i >> 6, c = i & 63;
        int idx = ((r >> 3) - (c >> 3) + 7) * 15 + ((r & 7) - (c & 7) + 7);
        g_bias6[h * NTOK * NTOK + i] = rpb[idx * HEADS + h];
    }
}

// ===========================================================================
// GEMM (TN): C[M,N] = A[M,180] @ B[N,180]^T + bias[N]; optional tf32-round
// of the output. Tile 128x64, 128 threads (4 warps), 2-stage cp.async
// pipeline. Register-cap math: 126 regs -> 4 CTAs/SM = 4 warps/SMSP.
// smem: 2 stages x (128+64) rows x 36 words = 55296 B; 4 CTAs = 221 KB/SM.
// ===========================================================================
#define GROWS 36
#define GSTAGE_WORDS (192 * GROWS)
#define GNITER 6

__global__ __launch_bounds__(128, 4) void mma_gemm_tn(
    const float* __restrict__ A, const float* __restrict__ B,
    const float* __restrict__ bias, float* __restrict__ C, int N, int roundOut)
{
    extern __shared__ float sm[];
    const int tid = threadIdx.x;
    const int row0 = blockIdx.y * 128;
    const int col0 = blockIdx.x * 64;

    const unsigned sbase = (unsigned)__cvta_generic_to_shared(sm);

    auto stage_load = [&](int s, int ki) {
        const int k0 = ki * 32;
        const unsigned stW = sbase + (unsigned)(s * GSTAGE_WORDS) * 4u;
#pragma unroll
        for (int j = 0; j < 12; j++) {
            int idx = tid + j * 128;            // 0..1535
            int c4 = idx & 7;
            int gk = k0 + c4 * 4;
            int gkc = gk <= 176 ? gk : 176;
            if (idx < 1024) {
                int r = idx >> 3;               // A row 0..127
                int bytes = (gk <= 176) ? 16 : 0;
                const float* src = A + (size_t)(row0 + r) * CDIM + gkc;
                cp_async16(stW + (unsigned)(r * GROWS + c4 * 4) * 4u, src, bytes);
            } else {
                int r = (idx - 1024) >> 3;      // B row 0..63
                int nn = col0 + r;
                int ok = (nn < N) && (gk <= 176);
                const float* src = B + (size_t)(ok ? nn : 0) * CDIM + gkc;
                cp_async16(stW + (unsigned)((128 + r) * GROWS + c4 * 4) * 4u,
                           src, ok ? 16 : 0);
            }
        }
    };

    stage_load(0, 0); cp_commit();

    const int warp = tid >> 5;
    const int lane = tid & 31;
    const int wm = warp & 1;          // 0..1 -> 64 rows
    const int wn = warp >> 1;         // 0..1 -> 32 cols
    const int g = lane >> 2;
    const int t = lane & 3;

    float acc[4][4][4];
#pragma unroll
    for (int mt = 0; mt < 4; mt++)
#pragma unroll
        for (int nt = 0; nt < 4; nt++)
#pragma unroll
            for (int e = 0; e < 4; e++) acc[mt][nt][e] = 0.f;

#pragma unroll 1
    for (int ks = 0; ks < GNITER; ks++) {
        if (ks + 1 < GNITER) {
            stage_load((ks + 1) & 1, ks + 1);
            cp_commit();
            cp_wait1();
        } else {
            cp_wait0();
        }
        __syncthreads();

        const float* sA = sm + (ks & 1) * GSTAGE_WORDS;
        const float* sB = sA + 128 * GROWS;

#pragma unroll
        for (int step = 0; step < 4; step++) {
            const int kb = step * 8;
            float a[4][4], b[4][2];
#pragma unroll
            for (int mt = 0; mt < 4; mt++) {
                int base = (wm * 64 + mt * 16 + g) * GROWS + kb + t;
                a[mt][0] = sA[base];
                a[mt][1] = sA[base + 8 * GROWS];
                a[mt][2] = sA[base + 4];
                a[mt][3] = sA[base + 8 * GROWS + 4];
            }
#pragma unroll
            for (int nt = 0; nt < 4; nt++) {
                int bb = (wn * 32 + nt * 8 + g) * GROWS + kb + t;
                b[nt][0] = sB[bb];
                b[nt][1] = sB[bb + 4];
            }
#pragma unroll
            for (int mt = 0; mt < 4; mt++)
#pragma unroll
                for (int nt = 0; nt < 4; nt++)
                    mma_tf32(acc[mt][nt], a[mt], b[nt]);
        }
        __syncthreads();
    }

#pragma unroll
    for (int mt = 0; mt < 4; mt++) {
#pragma unroll
        for (int nt = 0; nt < 4; nt++) {
            int row = row0 + wm * 64 + mt * 16 + g;
            int col = col0 + wn * 32 + nt * 8 + 2 * t;
            if (col < N) {
                float b0 = bias[col], b1 = bias[col + 1];
                float e0 = acc[mt][nt][0] + b0, e1 = acc[mt][nt][1] + b1;
                float e2 = acc[mt][nt][2] + b0, e3 = acc[mt][nt][3] + b1;
                if (roundOut) {
                    e0 = f2tf32(e0); e1 = f2tf32(e1);
                    e2 = f2tf32(e2); e3 = f2tf32(e3);
                }
                *(float2*)(C + (size_t)row * N + col) = make_float2(e0, e1);
                *(float2*)(C + (size_t)(row + 8) * N + col) = make_float2(e2, e3);
            }
        }
    }
}

// ===========================================================================
// MMA attention (R13 structure — proven fastest). 1D grid, wi-major block
// order for mask L2 residency. qkv arrives tf32-rounded and q-pre-scaled,
// so staging is a pure copy. Output tf32-rounded for the proj GEMM.
// smem: sQ[64][36] @0, sK @2304, sV @4608, sBM[64][68] @6912 (bias+mask,
// per-warp stripes reused for P). 45056 B -> 5 CTAs/SM (20 warps).
// ===========================================================================
#define ASM_K 2304
#define ASM_V 4608
#define ASM_B 6912
#define ATT_SMEM_FLOATS 11264

__global__ __launch_bounds__(128) void attn_mma_kernel(
    const float* __restrict__ qkv, const float* __restrict__ mask,
    float* __restrict__ out)
{
    extern __shared__ float sm[];
    // block remap: b -> (wi, img, h), wi slowest
    const int b = blockIdx.x;
    const int wi = b / (8 * HEADS);
    const int sub = b - wi * (8 * HEADS);
    const int img = sub / HEADS;
    const int h = sub - img * HEADS;
    const int w = img * NW_PER_IMG + wi;

    const int tid = threadIdx.x;
    const int ws = tid >> 5;
    const int lane = tid & 31;
    const int g = lane >> 2;
    const int t = lane & 3;

    // ---- stage q/k/v (pure copy; already rounded + scaled) ----
    for (int i = tid; i < 2880; i += 128) {
        int arr = i / 960;                     // 0=q 1=k 2=v
        int rem = i - arr * 960;
        int r = rem / 15, c2 = rem - r * 15;
        float2 v = *(const float2*)(qkv + (size_t)(w * NTOK + r) * (3 * CDIM)
                                    + arr * CDIM + h * HD + c2 * 2);
        *(float2*)(sm + arr * 2304 + r * 36 + c2 * 2) = v;
    }
    // zero pad d=30,31
    for (int i = tid; i < 384; i += 128) {
        int arr = i >> 7, rem = i & 127;
        int r = rem >> 1, d = 30 + (rem & 1);
        sm[arr * 2304 + r * 36 + d] = 0.f;
    }
    // ---- combined bias tile: bias6[h] + mask[wi], coalesced float4 ----
    {
        const float4* mb = (const float4*)(mask + (size_t)wi * NTOK * NTOK);
        const float4* bb = (const float4*)(g_bias6 + h * NTOK * NTOK);
        for (int i = tid; i < 1024; i += 128) {
            float4 mv = mb[i];
            float4 bv = bb[i];
            int r = i >> 4, c0 = (i & 15) * 4;
            *(float4*)(sm + ASM_B + r * 68 + c0) =
                make_float4(mv.x + bv.x, mv.y + bv.y, mv.z + bv.z, mv.w + bv.w);
        }
    }
    __syncthreads();

    const int row_g = ws * 16 + g;

    // ---- Q a-fragments ----
    float qa[4][4];
#pragma unroll
    for (int kc = 0; kc < 4; kc++) {
        qa[kc][0] = sm[row_g * 36 + kc * 8 + t];
        qa[kc][1] = sm[(row_g + 8) * 36 + kc * 8 + t];
        qa[kc][2] = sm[row_g * 36 + kc * 8 + t + 4];
        qa[kc][3] = sm[(row_g + 8) * 36 + kc * 8 + t + 4];
    }

    // ---- preload bias+mask (own stripe) ----
    float2 bia0[8], bia1[8];
#pragma unroll
    for (int nt = 0; nt < 8; nt++) {
        bia0[nt] = *(const float2*)(sm + ASM_B + row_g * 68 + nt * 8 + 2 * t);
        bia1[nt] = *(const float2*)(sm + ASM_B + (row_g + 8) * 68 + nt * 8 + 2 * t);
    }
    __syncwarp();

    // ---- scores + exp + P store ----
    float rs0 = 0.f, rs1 = 0.f;
    float* sPw = sm + ASM_B + ws * 16 * 68;
#pragma unroll
    for (int nt = 0; nt < 8; nt++) {
        float acc[4] = {0.f, 0.f, 0.f, 0.f};
#pragma unroll
        for (int kc = 0; kc < 4; kc++) {
            float b2[2];
            b2[0] = sm[ASM_K + (nt * 8 + g) * 36 + kc * 8 + t];
            b2[1] = sm[ASM_K + (nt * 8 + g) * 36 + kc * 8 + t + 4];
            mma_tf32(acc, qa[kc], b2);
        }
        float p0 = f2tf32(__expf(acc[0] + bia0[nt].x));
        float p1 = f2tf32(__expf(acc[1] + bia0[nt].y));
        float p2 = f2tf32(__expf(acc[2] + bia1[nt].x));
        float p3 = f2tf32(__expf(acc[3] + bia1[nt].y));
        rs0 += p0 + p1;
        rs1 += p2 + p3;
        *(float2*)(sPw + g * 68 + nt * 8 + 2 * t) = make_float2(p0, p1);
        *(float2*)(sPw + (g + 8) * 68 + nt * 8 + 2 * t) = make_float2(p2, p3);
    }
    rs0 += __shfl_xor_sync(0xffffffffu, rs0, 1);
    rs0 += __shfl_xor_sync(0xffffffffu, rs0, 2);
    rs1 += __shfl_xor_sync(0xffffffffu, rs1, 1);
    rs1 += __shfl_xor_sync(0xffffffffu, rs1, 2);
    __syncwarp();

    // ---- PV ----
    float oacc[4][4];
#pragma unroll
    for (int nd = 0; nd < 4; nd++)
#pragma unroll
        for (int e = 0; e < 4; e++) oacc[nd][e] = 0.f;
#pragma unroll
    for (int kc = 0; kc < 8; kc++) {
        float a[4];
        a[0] = sPw[g * 68 + kc * 8 + t];
        a[1] = sPw[(g + 8) * 68 + kc * 8 + t];
        a[2] = sPw[g * 68 + kc * 8 + t + 4];
        a[3] = sPw[(g + 8) * 68 + kc * 8 + t + 4];
#pragma unroll
        for (int nd = 0; nd < 4; nd++) {
            float b2[2];
            b2[0] = sm[ASM_V + (kc * 8 + t) * 36 + nd * 8 + g];
            b2[1] = sm[ASM_V + (kc * 8 + t + 4) * 36 + nd * 8 + g];
            mma_tf32(oacc[nd], a, b2);
        }
    }

    // ---- normalize + write out (tf32-rounded for proj GEMM) ----
    const float inv0 = 1.f / rs0;
    const float inv1 = 1.f / rs1;
#pragma unroll
    for (int nd = 0; nd < 4; nd++) {
        int d = nd * 8 + 2 * t;
        if (d < HD) {
            float2 v0 = make_float2(f2tf32(oacc[nd][0] * inv0), f2tf32(oacc[nd][1] * inv0));
            float2 v1 = make_float2(f2tf32(oacc[nd][2] * inv1), f2tf32(oacc[nd][3] * inv1));
            *(float2*)(out + (size_t)(w * NTOK + row_g) * CDIM + h * HD + d) = v0;
            *(float2*)(out + (size_t)(w * NTOK + row_g + 8) * CDIM + h * HD + d) = v1;
        }
    }
}

// ===========================================================================
extern "C" void kernel_launch(void* const* d_in, const int* in_sizes, int n_in,
                              void* d_out, int out_size)
{
    const float* x      = (const float*)d_in[0];
    const float* mask   = (const float*)d_in[1];
    const float* qkv_w  = (const float*)d_in[2];
    const float* qkv_b  = (const float*)d_in[3];
    const float* proj_w = (const float*)d_in[4];
    const float* proj_b = (const float*)d_in[5];
    const float* rpb    = (const float*)d_in[6];
    float* out = (float*)d_out;

    void *p_qkv = nullptr, *p_att = nullptr, *p_wq = nullptr, *p_wp = nullptr, *p_bq = nullptr;
    cudaGetSymbolAddress(&p_qkv, g_qkv);
    cudaGetSymbolAddress(&p_att, g_att);
    cudaGetSymbolAddress(&p_wq, g_wq);
    cudaGetSymbolAddress(&p_wp, g_wp);
    cudaGetSymbolAddress(&p_bq, g_bq);
    float* qkv = (float*)p_qkv;
    float* att = (float*)p_att;   // rounded x, then attention output
    float* wq  = (float*)p_wq;
    float* wp  = (float*)p_wp;
    float* bq  = (float*)p_bq;

    const int M = NW * NTOK;                                  // 524288
    const int gemm_smem = 2 * GSTAGE_WORDS * sizeof(float);   // 55296
    const int attn_smem = ATT_SMEM_FLOATS * sizeof(float);    // 45056

    static bool attr_set = false;
    if (!attr_set) {
        cudaFuncSetAttribute(mma_gemm_tn,
                             cudaFuncAttributeMaxDynamicSharedMemorySize, gemm_smem);
        cudaFuncSetAttribute(attn_mma_kernel,
                             cudaFuncAttributeMaxDynamicSharedMemorySize, attn_smem);
        attr_set = true;
    }

    // 0) Prep: round x, round+scale qkv_w, round proj_w, scale qkv_b, expand rpb
    round_kernel<<<2048, 256>>>(x, att, M * CDIM / 4);
    round_wq_kernel<<<64, 256>>>(qkv_w, wq);
    round_kernel<<<32, 256>>>(proj_w, wp, CDIM * CDIM / 4);
    scale_bq_kernel<<<1, 3 * CDIM>>>(qkv_b);
    bias_expand_kernel<<<HEADS, 256>>>(rpb);

    // 1) QKV projection (output tf32-rounded, q pre-scaled via wq/bq)
    {
        dim3 grid((3 * CDIM + 63) / 64, M / 128);     // (9, 4096)
        mma_gemm_tn<<<grid, 128, gemm_smem>>>(att, wq, bq, qkv, 3 * CDIM, 1);
    }

    // 2) MMA attention (1D grid, wi-major)
    attn_mma_kernel<<<NW * HEADS, 128, attn_smem>>>(qkv, mask, att);

    // 3) Output projection
    {
        dim3 grid((CDIM + 63) / 64, M / 128);         // (3, 4096)
        mma_gemm_tn<<<grid, 128, gemm_smem>>>(att, wp, proj_b, out, CDIM, 0);
    }
}